// round 3
// baseline (speedup 1.0000x reference)
#include <cuda_runtime.h>
#include <cuda_bf16.h>

// Problem constants
#define BB 4
#define NN 8192
#define KK 16
#define CC 128
#define TT 3
#define BN (BB*NN)          // 32768 rows total

#define PW 132              // padded stride for 128-wide weight rows (float4-aligned, conflict-free)
#define PU 260              // padded stride for 256-wide weight rows
#define HS 20               // padded stride for H tile rows [i][k] (16B aligned, 2-way max conflict)

#define NSM 152
#define GRID2 (2*NSM)

// ---------------- device scratch (static globals; no runtime allocation) ----------------
__device__ float g_feat[BN*CC];   // current features
__device__ float g_GP[BN*CC];     // per-node gatherable part of edge layer-1
__device__ float g_bq[BN*CC];     // per-node center-dependent part (includes edge_b1)
__device__ float g_agg[BN*CC];    // max-aggregated edge features

// ---------------- f32x2 helpers (Blackwell packed FFMA2) ----------------
__device__ __forceinline__ unsigned long long ffma2(unsigned long long a, unsigned long long b,
                                                    unsigned long long c) {
    unsigned long long d;
    asm("fma.rn.f32x2 %0, %1, %2, %3;" : "=l"(d) : "l"(a), "l"(b), "l"(c));
    return d;
}
__device__ __forceinline__ float f2lo(unsigned long long v){ return __uint_as_float((unsigned)v); }
__device__ __forceinline__ float f2hi(unsigned long long v){ return __uint_as_float((unsigned)(v>>32)); }
__device__ __forceinline__ float f2red(unsigned long long v){ return f2lo(v)+f2hi(v); }
__device__ __forceinline__ unsigned long long bcast2(float f){
    unsigned long long r; unsigned u = __float_as_uint(f);
    asm("mov.b64 %0, {%1, %1};" : "=l"(r) : "r"(u));
    return r;
}

// =======================================================================
// K1a: offset MLP -> center -> bq  (per node)
//   h1 = relu(feat @ offW1^T + offb1); delta = h1 @ offW2^T + offb2
//   center = xyz + delta; bq = edge_b1 - W1xyz @ center
// =======================================================================
__global__ __launch_bounds__(128)
void k_offset_bq(const float* __restrict__ xyz,
                 const float* __restrict__ offW1, const float* __restrict__ offb1,
                 const float* __restrict__ offW2, const float* __restrict__ offb2,
                 const float* __restrict__ eW1,   // edge_W1[t]: (128, 131)
                 const float* __restrict__ eb1)
{
    extern __shared__ float sm[];
    float* sW1   = sm;                    // 128*PW
    float* sW2T  = sW1 + 128*PW;          // [d][i] : 3*128
    float* sW1xT = sW2T + 3*128;          // [d][j] : 3*128 (edge W1 xyz cols)
    float* sB1   = sW1xT + 3*128;         // 128
    float* sEB1  = sB1 + 128;             // 128
    float* sB2   = sEB1 + 128;            // 4
    float* sF    = sB2 + 4;               // 128
    float* sH    = sF + 128;              // 128
    float* sCen  = sH + 128;              // 4

    const int tid = threadIdx.x;

    for (int i = tid; i < 128*128; i += 128)
        sW1[(i>>7)*PW + (i&127)] = offW1[i];
    for (int i = tid; i < 3*128; i += 128) {
        int d = i >> 7, j = i & 127;
        sW2T[d*128 + j]  = offW2[d*128 + j];
        sW1xT[d*128 + j] = eW1[j*131 + d];
    }
    sB1[tid] = offb1[tid];
    sEB1[tid] = eb1[tid];
    if (tid < 3) sB2[tid] = offb2[tid];
    __syncthreads();

    for (int n = blockIdx.x; n < BN; n += gridDim.x) {
        if (tid < 32) ((float4*)sF)[tid] = ((const float4*)(g_feat + (size_t)n*CC))[tid];
        __syncthreads();

        // h1[j], j = tid
        {
            unsigned long long a0 = 0ull, a1 = 0ull;
            const ulonglong2* wv = (const ulonglong2*)(sW1 + tid*PW);
            const ulonglong2* fv = (const ulonglong2*)sF;
            #pragma unroll 8
            for (int i4 = 0; i4 < 32; i4++) {
                ulonglong2 w = wv[i4], f = fv[i4];
                a0 = ffma2(w.x, f.x, a0);
                a1 = ffma2(w.y, f.y, a1);
            }
            sH[tid] = fmaxf(sB1[tid] + f2red(a0) + f2red(a1), 0.f);
        }
        __syncthreads();

        // delta + center: 3 warps each reduce one output dim
        {
            int w = tid >> 5, l = tid & 31;
            if (w < 3) {
                float p = 0.f;
                #pragma unroll
                for (int i = 0; i < 4; i++) p += sH[l + 32*i] * sW2T[w*128 + l + 32*i];
                #pragma unroll
                for (int o = 16; o; o >>= 1) p += __shfl_down_sync(0xffffffffu, p, o);
                if (l == 0) sCen[w] = p + sB2[w] + xyz[(size_t)n*3 + w];
            }
        }
        __syncthreads();

        // bq[j]
        {
            float c0 = sCen[0], c1 = sCen[1], c2 = sCen[2];
            float bq = sEB1[tid] - c0*sW1xT[tid] - c1*sW1xT[128+tid] - c2*sW1xT[256+tid];
            g_bq[(size_t)n*CC + tid] = bq;
        }
        __syncthreads();
    }
}

// =======================================================================
// K1b: GP[n][j] = feat[n] . eW1_feat[j] + xyz[n] . eW1_xyz[j]
// =======================================================================
__global__ __launch_bounds__(128)
void k_gp(const float* __restrict__ xyz, const float* __restrict__ eW1)
{
    extern __shared__ float sm[];
    float* sW   = sm;                 // 128*PW (feature columns of edge W1)
    float* sWxT = sW + 128*PW;        // [d][j]
    float* sF   = sWxT + 3*128;       // 128

    const int tid = threadIdx.x;
    for (int i = tid; i < 128*128; i += 128) {
        int r = i >> 7, c = i & 127;
        sW[r*PW + c] = eW1[r*131 + 3 + c];
    }
    for (int i = tid; i < 3*128; i += 128) {
        int d = i >> 7, j = i & 127;
        sWxT[d*128 + j] = eW1[j*131 + d];
    }
    __syncthreads();

    for (int n = blockIdx.x; n < BN; n += gridDim.x) {
        if (tid < 32) ((float4*)sF)[tid] = ((const float4*)(g_feat + (size_t)n*CC))[tid];
        __syncthreads();
        float x0 = xyz[(size_t)n*3], x1 = xyz[(size_t)n*3+1], x2 = xyz[(size_t)n*3+2];
        float base = x0*sWxT[tid] + x1*sWxT[128+tid] + x2*sWxT[256+tid];
        unsigned long long a0 = 0ull, a1 = 0ull;
        const ulonglong2* wv = (const ulonglong2*)(sW + tid*PW);
        const ulonglong2* fv = (const ulonglong2*)sF;
        #pragma unroll 8
        for (int i4 = 0; i4 < 32; i4++) {
            ulonglong2 w = wv[i4], f = fv[i4];
            a0 = ffma2(w.x, f.x, a0);
            a1 = ffma2(w.y, f.y, a1);
        }
        g_GP[(size_t)n*CC + tid] = base + f2red(a0) + f2red(a1);
        __syncthreads();
    }
}

// =======================================================================
// K2: edge layer-2 + max over K
//   h[k] = relu(GP[idx[n,k]] + bq[n]); e[j,k] = W2[j] . h[k]; agg[j] = max_k e + b2[j]
//   GEMM mapping: 128 threads = (64 output pairs) x (2 k-halves), f32x2 accumulators.
// =======================================================================
__global__ __launch_bounds__(128)
void k_edge(const int* __restrict__ knn,
            const float* __restrict__ eW2, const float* __restrict__ eb2)
{
    extern __shared__ float sm[];
    float* sW   = sm;                 // 128*PW
    float* sH   = sW + 128*PW;        // [i][k] stride HS : 128*HS
    float* sB2  = sH + 128*HS;        // 128
    float* sRed = sB2 + 128;          // 256

    const int tid = threadIdx.x;
    for (int i = tid; i < 128*128; i += 128)
        sW[(i>>7)*PW + (i&127)] = eW2[i];
    sB2[tid] = eb2[tid];
    __syncthreads();

    const int kk = tid & 15;          // assembly: k index
    const int cc = tid >> 4;          // assembly: 16-feature chunk 0..7
    const int jj = tid & 63;          // gemm: output pair (jj, jj+64)
    const int kh = tid >> 6;          // gemm: k half 0..1

    for (int n = blockIdx.x; n < BN; n += gridDim.x) {
        // ---- assemble H = relu(GP[gather] + bq) transposed to [i][k] ----
        {
            int b = n >> 13;                               // n / NN
            int gid = (b << 13) + knn[(size_t)n*KK + kk];
            const float4* gp = (const float4*)(g_GP + (size_t)gid*CC + cc*16);
            const float4* bq = (const float4*)(g_bq + (size_t)n*CC  + cc*16);
            #pragma unroll
            for (int u = 0; u < 4; u++) {
                float4 g = gp[u], q = bq[u];
                int i0 = cc*16 + u*4;
                sH[(i0+0)*HS + kk] = fmaxf(g.x + q.x, 0.f);
                sH[(i0+1)*HS + kk] = fmaxf(g.y + q.y, 0.f);
                sH[(i0+2)*HS + kk] = fmaxf(g.z + q.z, 0.f);
                sH[(i0+3)*HS + kk] = fmaxf(g.w + q.w, 0.f);
            }
        }
        __syncthreads();

        // ---- GEMM 128x16x128 with per-thread (2 outputs x 8 k) f32x2 tiles ----
        {
            unsigned long long a0[4] = {0ull,0ull,0ull,0ull};
            unsigned long long a1[4] = {0ull,0ull,0ull,0ull};
            const float* wr0 = sW + jj*PW;
            const float* wr1 = sW + (jj+64)*PW;
            const float* hb  = sH + kh*8;
            #pragma unroll 4
            for (int i4 = 0; i4 < 32; i4++) {
                float4 w0 = ((const float4*)wr0)[i4];
                float4 w1 = ((const float4*)wr1)[i4];
                #pragma unroll
                for (int q = 0; q < 4; q++) {
                    float w0q = (q==0)?w0.x:(q==1)?w0.y:(q==2)?w0.z:w0.w;
                    float w1q = (q==0)?w1.x:(q==1)?w1.y:(q==2)?w1.z:w1.w;
                    unsigned long long wp0 = bcast2(w0q);
                    unsigned long long wp1 = bcast2(w1q);
                    const ulonglong2* hv = (const ulonglong2*)(hb + (i4*4+q)*HS);
                    ulonglong2 hA = hv[0], hB = hv[1];
                    a0[0] = ffma2(wp0, hA.x, a0[0]); a0[1] = ffma2(wp0, hA.y, a0[1]);
                    a0[2] = ffma2(wp0, hB.x, a0[2]); a0[3] = ffma2(wp0, hB.y, a0[3]);
                    a1[0] = ffma2(wp1, hA.x, a1[0]); a1[1] = ffma2(wp1, hA.y, a1[1]);
                    a1[2] = ffma2(wp1, hB.x, a1[2]); a1[3] = ffma2(wp1, hB.y, a1[3]);
                }
            }
            float m0 = -3.4e38f, m1 = -3.4e38f;
            #pragma unroll
            for (int p = 0; p < 4; p++) {
                m0 = fmaxf(m0, fmaxf(f2lo(a0[p]), f2hi(a0[p])));
                m1 = fmaxf(m1, fmaxf(f2lo(a1[p]), f2hi(a1[p])));
            }
            sRed[kh*128 + jj]      = m0;
            sRed[kh*128 + jj + 64] = m1;
        }
        __syncthreads();

        g_agg[(size_t)n*CC + tid] = fmaxf(sRed[tid], sRed[128 + tid]) + sB2[tid];
        __syncthreads();
    }
}

// =======================================================================
// K3: update MLP + residual
//   u = [agg, feat]; h = relu(uW1 @ u + ub1); feat += uW2 @ h + ub2
//   256 threads: (128 outputs) x (2 input halves)
// =======================================================================
__global__ __launch_bounds__(256)
void k_update(const float* __restrict__ W1, const float* __restrict__ b1,
              const float* __restrict__ W2, const float* __restrict__ b2,
              float* __restrict__ outp, int write_out)
{
    extern __shared__ float sm[];
    float* sW1 = sm;                 // 128*PU
    float* sW2 = sW1 + 128*PU;       // 128*PW
    float* sU  = sW2 + 128*PW;       // 256
    float* sH  = sU + 256;           // 128
    float* sP  = sH + 128;           // 256
    float* sB1 = sP + 256;           // 128
    float* sB2 = sB1 + 128;          // 128

    const int tid = threadIdx.x;
    for (int i = tid; i < 128*256; i += 256)
        sW1[(i>>8)*PU + (i&255)] = W1[i];
    for (int i = tid; i < 128*128; i += 256)
        sW2[(i>>7)*PW + (i&127)] = W2[i];
    if (tid < 128) { sB1[tid] = b1[tid]; sB2[tid] = b2[tid]; }
    __syncthreads();

    const int j = tid & 127;
    const int half = tid >> 7;

    for (int n = blockIdx.x; n < BN; n += gridDim.x) {
        if (tid < 32)      ((float4*)sU)[tid] = ((const float4*)(g_agg  + (size_t)n*CC))[tid];
        else if (tid < 64) ((float4*)sU)[tid] = ((const float4*)(g_feat + (size_t)n*CC))[tid-32];
        __syncthreads();

        // layer 1 (split over 2 input halves of 128)
        {
            unsigned long long a0 = 0ull, a1 = 0ull;
            const ulonglong2* wv = (const ulonglong2*)(sW1 + j*PU + half*128);
            const ulonglong2* uv = (const ulonglong2*)(sU + half*128);
            #pragma unroll 8
            for (int i4 = 0; i4 < 32; i4++) {
                ulonglong2 w = wv[i4], u = uv[i4];
                a0 = ffma2(w.x, u.x, a0);
                a1 = ffma2(w.y, u.y, a1);
            }
            sP[half*128 + j] = f2red(a0) + f2red(a1);
        }
        __syncthreads();
        if (half == 0) sH[j] = fmaxf(sB1[j] + sP[j] + sP[128+j], 0.f);
        __syncthreads();

        // layer 2 (split over 2 input halves of 64)
        {
            unsigned long long a0 = 0ull, a1 = 0ull;
            const ulonglong2* wv = (const ulonglong2*)(sW2 + j*PW + half*64);
            const ulonglong2* hv = (const ulonglong2*)(sH + half*64);
            #pragma unroll 8
            for (int i4 = 0; i4 < 16; i4++) {
                ulonglong2 w = wv[i4], h = hv[i4];
                a0 = ffma2(w.x, h.x, a0);
                a1 = ffma2(w.y, h.y, a1);
            }
            sP[half*128 + j] = f2red(a0) + f2red(a1);
        }
        __syncthreads();
        if (half == 0) {
            float v = sU[128 + j] + sB2[j] + sP[j] + sP[128+j];
            g_feat[(size_t)n*CC + j] = v;
            if (write_out) outp[(size_t)n*CC + j] = v;
        }
        __syncthreads();
    }
}

// =======================================================================
// launch
// =======================================================================
extern "C" void kernel_launch(void* const* d_in, const int* in_sizes, int n_in,
                              void* d_out, int out_size) {
    const float* xyz   = (const float*)d_in[0];
    const float* feat0 = (const float*)d_in[1];
    const int*   knn   = (const int*)d_in[2];
    const float* offW1 = (const float*)d_in[3];
    const float* offb1 = (const float*)d_in[4];
    const float* offW2 = (const float*)d_in[5];
    const float* offb2 = (const float*)d_in[6];
    const float* eW1   = (const float*)d_in[7];
    const float* eb1   = (const float*)d_in[8];
    const float* eW2   = (const float*)d_in[9];
    const float* eb2   = (const float*)d_in[10];
    const float* uW1   = (const float*)d_in[11];
    const float* ub1   = (const float*)d_in[12];
    const float* uW2   = (const float*)d_in[13];
    const float* ub2   = (const float*)d_in[14];
    float* outp = (float*)d_out;

    const size_t SMEM_K1A = (size_t)(128*PW + 3*128 + 3*128 + 128 + 128 + 4 + 128 + 128 + 4) * 4;
    const size_t SMEM_K1B = (size_t)(128*PW + 3*128 + 128) * 4;
    const size_t SMEM_K2  = (size_t)(128*PW + 128*HS + 128 + 256) * 4;
    const size_t SMEM_K3  = (size_t)(128*PU + 128*PW + 256 + 128 + 256 + 128 + 128) * 4;

    cudaFuncSetAttribute(k_offset_bq, cudaFuncAttributeMaxDynamicSharedMemorySize, (int)SMEM_K1A);
    cudaFuncSetAttribute(k_gp,        cudaFuncAttributeMaxDynamicSharedMemorySize, (int)SMEM_K1B);
    cudaFuncSetAttribute(k_edge,      cudaFuncAttributeMaxDynamicSharedMemorySize, (int)SMEM_K2);
    cudaFuncSetAttribute(k_update,    cudaFuncAttributeMaxDynamicSharedMemorySize, (int)SMEM_K3);

    cudaMemcpyToSymbolAsync(g_feat, feat0, sizeof(float)*BN*CC, 0, cudaMemcpyDeviceToDevice, 0);

    for (int t = 0; t < TT; t++) {
        k_offset_bq<<<GRID2, 128, SMEM_K1A>>>(xyz, offW1, offb1, offW2, offb2,
                                              eW1 + (size_t)t*CC*(3+CC), eb1 + (size_t)t*CC);
        k_gp<<<GRID2, 128, SMEM_K1B>>>(xyz, eW1 + (size_t)t*CC*(3+CC));
        k_edge<<<GRID2, 128, SMEM_K2>>>(knn, eW2 + (size_t)t*CC*CC, eb2 + (size_t)t*CC);
        k_update<<<NSM, 256, SMEM_K3>>>(uW1 + (size_t)t*CC*2*CC, ub1 + (size_t)t*CC,
                                        uW2 + (size_t)t*CC*CC, ub2 + (size_t)t*CC,
                                        outp, (t == TT-1) ? 1 : 0);
    }
}

// round 4
// speedup vs baseline: 2.1574x; 2.1574x over previous
#include <cuda_runtime.h>
#include <cuda_bf16.h>

// Problem constants
#define BB 4
#define NN 8192
#define KK 16
#define CC 128
#define TT 3
#define BN (BB*NN)          // 32768 rows total

#define NSM 152

// ---------------- device scratch ----------------
__device__ float g_feat[BN*CC];
__device__ float g_GP[BN*CC];     // gatherable part of edge layer-1 (incl. xyz term)
__device__ float g_bq[BN*CC];     // center part (incl. edge_b1)
__device__ float g_agg[BN*CC];
__device__ float g_h[BN*CC];      // update hidden
// transposed (k-major) weights
__device__ float g_offW1T[128*128];
__device__ float g_eW1fT[TT*128*128];
__device__ float g_eW2T[TT*128*128];
__device__ float g_uW1T[TT*256*128];
__device__ float g_uW2T[TT*128*128];

// ---------------- f32x2 helpers ----------------
__device__ __forceinline__ unsigned long long ffma2(unsigned long long a, unsigned long long b,
                                                    unsigned long long c) {
    unsigned long long d;
    asm("fma.rn.f32x2 %0, %1, %2, %3;" : "=l"(d) : "l"(a), "l"(b), "l"(c));
    return d;
}
__device__ __forceinline__ float f2lo(unsigned long long v){ return __uint_as_float((unsigned)v); }
__device__ __forceinline__ float f2hi(unsigned long long v){ return __uint_as_float((unsigned)(v>>32)); }
__device__ __forceinline__ unsigned long long bcast2(float f){
    unsigned long long r; unsigned u = __float_as_uint(f);
    asm("mov.b64 %0, {%1, %1};" : "=l"(r) : "r"(u));
    return r;
}

// col base for accumulator slot p (p=0,1 -> low 64 cols; p=2,3 -> high 64 cols)
__device__ __forceinline__ int colbase(int tx, int p) {
    return (p < 2) ? (tx*4 + p*2) : (64 + tx*4 + (p-2)*2);
}

// ---------------- shared GEMM core ----------------
// C[r][j] = sum_k sAT[k][r] * sBT[k][j]   (both tiles 128x128, k-major, stride 128)
// 256 threads: ty=tid>>4 (rows r=ty*8+u), tx=tid&15 (cols tx*4..+3 and 64+tx*4..+3)
__device__ __forceinline__ void gemm128(const float* __restrict__ sAT,
                                        const float* __restrict__ sBT,
                                        unsigned long long acc[8][4],
                                        int ty, int tx)
{
    const float* aptr = sAT + ty*8;
    const float* bptr = sBT + tx*4;
    #pragma unroll 8
    for (int k = 0; k < 128; k++) {
        float4 a0 = *(const float4*)(aptr + k*128);
        float4 a1 = *(const float4*)(aptr + k*128 + 4);
        ulonglong2 b0 = *(const ulonglong2*)(bptr + k*128);
        ulonglong2 b1 = *(const ulonglong2*)(bptr + k*128 + 64);
        float av[8] = {a0.x,a0.y,a0.z,a0.w,a1.x,a1.y,a1.z,a1.w};
        #pragma unroll
        for (int u = 0; u < 8; u++) {
            unsigned long long ap = bcast2(av[u]);
            acc[u][0] = ffma2(ap, b0.x, acc[u][0]);
            acc[u][1] = ffma2(ap, b0.y, acc[u][1]);
            acc[u][2] = ffma2(ap, b1.x, acc[u][2]);
            acc[u][3] = ffma2(ap, b1.y, acc[u][3]);
        }
    }
}

__device__ __forceinline__ void zero_acc(unsigned long long acc[8][4]) {
    #pragma unroll
    for (int u = 0; u < 8; u++)
        #pragma unroll
        for (int p = 0; p < 4; p++) acc[u][p] = 0ull;
}

// scatter-transpose a 128x128 row-major gmem tile into smem [k][r]
__device__ __forceinline__ void load_AT(const float* __restrict__ X,  // X = base + n0*128
                                        float* __restrict__ sAT, int tid)
{
    int r = tid & 127, half = tid >> 7;
    const float4* row = (const float4*)(X + (size_t)r*128) + half*16;
    #pragma unroll
    for (int c = 0; c < 16; c++) {
        float4 v = row[c];
        int i = half*64 + c*4;
        sAT[(i+0)*128 + r] = v.x;
        sAT[(i+1)*128 + r] = v.y;
        sAT[(i+2)*128 + r] = v.z;
        sAT[(i+3)*128 + r] = v.w;
    }
}

// copy a pre-transposed 128x128 weight tile gmem -> smem
__device__ __forceinline__ void load_W(const float* __restrict__ WT, float* __restrict__ sBT, int tid) {
    #pragma unroll
    for (int i = tid; i < 128*32; i += 256)
        ((float4*)sBT)[i] = ((const float4*)WT)[i];
}

// =======================================================================
// setup: transpose all weights into k-major scratch
// =======================================================================
__global__ void k_transpose(const float* __restrict__ offW1, const float* __restrict__ eW1,
                            const float* __restrict__ eW2,  const float* __restrict__ uW1,
                            const float* __restrict__ uW2)
{
    int tid = blockIdx.x*blockDim.x + threadIdx.x;  // 0..16383
    int k = tid >> 7, j = tid & 127;
    g_offW1T[tid] = offW1[j*128 + k];
    #pragma unroll
    for (int t = 0; t < TT; t++) {
        g_eW1fT[t*16384 + tid] = eW1[t*128*131 + j*131 + 3 + k];
        g_eW2T [t*16384 + tid] = eW2[t*16384 + j*128 + k];
        g_uW2T [t*16384 + tid] = uW2[t*16384 + j*128 + k];
        g_uW1T [t*32768 + tid]         = uW1[t*128*256 + j*256 + k];
        g_uW1T [t*32768 + 16384 + tid] = uW1[t*128*256 + j*256 + 128 + k];
    }
}

// =======================================================================
// Kernel A: offset MLP -> center -> bq  AND  GP, fused.  Tile = 128 nodes.
// =======================================================================
__global__ __launch_bounds__(256, 1)
void kA(const float* __restrict__ xyz,
        const float* __restrict__ offb1, const float* __restrict__ offW2,
        const float* __restrict__ offb2,
        const float* __restrict__ eW1, const float* __restrict__ eb1, int t)
{
    extern __shared__ float sm[];
    float* sFT    = sm;                 // 16384  feat^T [k][r]
    float* sW1    = sFT + 16384;        // 16384  offW1T (persistent)
    float* sWe    = sW1 + 16384;        // 16384  eW1fT  (persistent)
    float* sP     = sWe + 16384;        // 6144   delta partials [tx][r*3+d]
    float* sCen   = sP + 6144;          // 384    center [r*3+d]
    float* sXyz   = sCen + 384;         // 384    xyz tile [r*3+d]
    float* sW1x   = sXyz + 384;         // 384    eW1 xyz cols [d][j]
    float* sOffW2 = sW1x + 384;         // 384    [d][j]
    float* sB1    = sOffW2 + 384;       // 128
    float* sEB1   = sB1 + 128;          // 128
    float* sB2    = sEB1 + 128;         // 16

    const int tid = threadIdx.x;
    const int ty = tid >> 4, tx = tid & 15;

    load_W(g_offW1T, sW1, tid);
    load_W(g_eW1fT + t*16384, sWe, tid);
    for (int i = tid; i < 384; i += 256) {
        int d = i >> 7, j = i & 127;
        sW1x[i] = eW1[j*131 + d];
        sOffW2[i] = offW2[i];   // (3,128) row-major, same linear layout
    }
    if (tid < 128) { sB1[tid] = offb1[tid]; sEB1[tid] = eb1[tid]; }
    if (tid < 3) sB2[tid] = offb2[tid];
    __syncthreads();

    for (int tile = blockIdx.x; tile < BN/128; tile += gridDim.x) {
        const int n0 = tile * 128;
        load_AT(g_feat + (size_t)n0*128, sFT, tid);
        for (int i = tid; i < 384; i += 256) sXyz[i] = xyz[(size_t)n0*3 + i];
        __syncthreads();

        unsigned long long acc[8][4];
        zero_acc(acc);
        gemm128(sFT, sW1, acc, ty, tx);

        // h1 = relu(acc+b1); delta partials over this thread's 8 cols
        #pragma unroll
        for (int u = 0; u < 8; u++) {
            int r = ty*8 + u;
            float p0 = 0.f, p1 = 0.f, p2 = 0.f;
            #pragma unroll
            for (int p = 0; p < 4; p++) {
                int jb = colbase(tx, p);
                float lo = f2lo(acc[u][p]), hi = f2hi(acc[u][p]);
                float h0 = fmaxf(lo + sB1[jb], 0.f);
                float h1v = fmaxf(hi + sB1[jb+1], 0.f);
                p0 += h0*sOffW2[jb]     + h1v*sOffW2[jb+1];
                p1 += h0*sOffW2[128+jb] + h1v*sOffW2[128+jb+1];
                p2 += h0*sOffW2[256+jb] + h1v*sOffW2[256+jb+1];
            }
            sP[tx*384 + r*3 + 0] = p0;
            sP[tx*384 + r*3 + 1] = p1;
            sP[tx*384 + r*3 + 2] = p2;
        }
        __syncthreads();

        // reduce delta over tx, form center = xyz + delta + offb2
        if (tid < 192) {
            #pragma unroll
            for (int q = 0; q < 2; q++) {
                int o = tid*2 + q;  // 0..383 = r*3+d
                float s = 0.f;
                #pragma unroll
                for (int x = 0; x < 16; x++) s += sP[x*384 + o];
                int d = o - 3*(o/3);
                sCen[o] = s + sB2[d] + sXyz[o];
            }
        }
        __syncthreads();

        // GP GEMM (feature part), epilogue adds xyz part, writes GP and bq
        zero_acc(acc);
        gemm128(sFT, sWe, acc, ty, tx);

        #pragma unroll
        for (int u = 0; u < 8; u++) {
            int r = ty*8 + u;
            float x0 = sXyz[r*3], x1 = sXyz[r*3+1], x2 = sXyz[r*3+2];
            float c0 = sCen[r*3], c1 = sCen[r*3+1], c2 = sCen[r*3+2];
            #pragma unroll
            for (int p = 0; p < 4; p++) {
                int jb = colbase(tx, p);
                float lo = f2lo(acc[u][p]), hi = f2hi(acc[u][p]);
                float w0a = sW1x[jb],     w0b = sW1x[jb+1];
                float w1a = sW1x[128+jb], w1b = sW1x[128+jb+1];
                float w2a = sW1x[256+jb], w2b = sW1x[256+jb+1];
                float2 gp = make_float2(lo + x0*w0a + x1*w1a + x2*w2a,
                                        hi + x0*w0b + x1*w1b + x2*w2b);
                float2 bq = make_float2(sEB1[jb]   - (c0*w0a + c1*w1a + c2*w2a),
                                        sEB1[jb+1] - (c0*w0b + c1*w1b + c2*w2b));
                *(float2*)(g_GP + (size_t)(n0+r)*128 + jb) = gp;
                *(float2*)(g_bq + (size_t)(n0+r)*128 + jb) = bq;
            }
        }
        __syncthreads();
    }
}

// =======================================================================
// Kernel B: edge layer-2 + max over K.  Tile = 8 nodes (128 gathered rows).
// =======================================================================
__global__ __launch_bounds__(256, 1)
void kB(const int* __restrict__ knn, const float* __restrict__ eb2, int t)
{
    extern __shared__ float sm[];
    float* sHT  = sm;                // 16384  H^T [i][r] ; reused as C [r][j]
    float* sW   = sHT + 16384;       // 16384  eW2T (persistent)
    float* sBq  = sW + 16384;        // 1024   bq tile (8 nodes x 128)
    float* sB2  = sBq + 1024;        // 128
    int*   sIdx = (int*)(sB2 + 128); // 128

    const int tid = threadIdx.x;
    const int ty = tid >> 4, tx = tid & 15;

    load_W(g_eW2T + t*16384, sW, tid);
    if (tid < 128) sB2[tid] = eb2[tid];
    __syncthreads();

    for (int tile = blockIdx.x; tile < BN/8; tile += gridDim.x) {
        const int n0 = tile * 8;
        if (tid < 128) sIdx[tid] = knn[(size_t)n0*KK + tid];
        ((float4*)sBq)[tid] = ((const float4*)(g_bq + (size_t)n0*128))[tid];
        __syncthreads();

        // assemble H^T: row r = (node m=r/16, k=r%16); h = relu(GP[gid] + bq[m])
        {
            int r = tid & 127, half = tid >> 7;
            int m = r >> 4;
            int gn = n0 + m;
            int gid = ((gn >> 13) << 13) + sIdx[r];
            const float4* src = (const float4*)(g_GP + (size_t)gid*128) + half*16;
            const float4* bqr = (const float4*)(sBq + m*128) + half*16;
            #pragma unroll
            for (int c = 0; c < 16; c++) {
                float4 v = src[c], q = bqr[c];
                int i = half*64 + c*4;
                sHT[(i+0)*128 + r] = fmaxf(v.x + q.x, 0.f);
                sHT[(i+1)*128 + r] = fmaxf(v.y + q.y, 0.f);
                sHT[(i+2)*128 + r] = fmaxf(v.z + q.z, 0.f);
                sHT[(i+3)*128 + r] = fmaxf(v.w + q.w, 0.f);
            }
        }
        __syncthreads();

        unsigned long long acc[8][4];
        zero_acc(acc);
        gemm128(sHT, sW, acc, ty, tx);
        __syncthreads();  // all reads of sHT done -> reuse as C

        #pragma unroll
        for (int u = 0; u < 8; u++) {
            int r = ty*8 + u;
            #pragma unroll
            for (int p = 0; p < 4; p++) {
                int jb = colbase(tx, p);
                *(float2*)(sHT + r*128 + jb) = make_float2(f2lo(acc[u][p]), f2hi(acc[u][p]));
            }
        }
        __syncthreads();

        // max over 16 k per node + bias
        {
            int c = tid & 127, ug = tid >> 7;
            #pragma unroll
            for (int w = 0; w < 4; w++) {
                int m = ug*4 + w;
                float mx = -3.4e38f;
                #pragma unroll
                for (int k = 0; k < 16; k++)
                    mx = fmaxf(mx, sHT[(m*16 + k)*128 + c]);
                g_agg[(size_t)(n0+m)*128 + c] = mx + sB2[c];
            }
        }
        __syncthreads();
    }
}

// =======================================================================
// Kernel C1: update layer 1 (K=256 as two accumulating chunks) -> g_h
// =======================================================================
__global__ __launch_bounds__(256, 1)
void kC1(const float* __restrict__ ub1, int t)
{
    extern __shared__ float sm[];
    float* sAT = sm;            // 16384
    float* sW0 = sAT + 16384;   // 16384 uW1T chunk0 (persistent)
    float* sW1 = sW0 + 16384;   // 16384 uW1T chunk1 (persistent)
    float* sB1 = sW1 + 16384;   // 128

    const int tid = threadIdx.x;
    const int ty = tid >> 4, tx = tid & 15;

    load_W(g_uW1T + t*32768, sW0, tid);
    load_W(g_uW1T + t*32768 + 16384, sW1, tid);
    if (tid < 128) sB1[tid] = ub1[tid];
    __syncthreads();

    for (int tile = blockIdx.x; tile < BN/128; tile += gridDim.x) {
        const int n0 = tile * 128;
        unsigned long long acc[8][4];
        zero_acc(acc);

        load_AT(g_agg + (size_t)n0*128, sAT, tid);
        __syncthreads();
        gemm128(sAT, sW0, acc, ty, tx);
        __syncthreads();

        load_AT(g_feat + (size_t)n0*128, sAT, tid);
        __syncthreads();
        gemm128(sAT, sW1, acc, ty, tx);

        #pragma unroll
        for (int u = 0; u < 8; u++) {
            int r = ty*8 + u;
            #pragma unroll
            for (int p = 0; p < 4; p++) {
                int jb = colbase(tx, p);
                float2 h = make_float2(fmaxf(f2lo(acc[u][p]) + sB1[jb],   0.f),
                                       fmaxf(f2hi(acc[u][p]) + sB1[jb+1], 0.f));
                *(float2*)(g_h + (size_t)(n0+r)*128 + jb) = h;
            }
        }
        __syncthreads();
    }
}

// =======================================================================
// Kernel C2: update layer 2 + residual -> g_feat (and output on last iter)
// =======================================================================
__global__ __launch_bounds__(256, 1)
void kC2(const float* __restrict__ ub2, float* __restrict__ outp, int write_out, int t)
{
    extern __shared__ float sm[];
    float* sAT = sm;            // 16384
    float* sW  = sAT + 16384;   // 16384 uW2T (persistent)
    float* sB2 = sW + 16384;    // 128

    const int tid = threadIdx.x;
    const int ty = tid >> 4, tx = tid & 15;

    load_W(g_uW2T + t*16384, sW, tid);
    if (tid < 128) sB2[tid] = ub2[tid];
    __syncthreads();

    for (int tile = blockIdx.x; tile < BN/128; tile += gridDim.x) {
        const int n0 = tile * 128;
        load_AT(g_h + (size_t)n0*128, sAT, tid);
        __syncthreads();

        unsigned long long acc[8][4];
        zero_acc(acc);
        gemm128(sAT, sW, acc, ty, tx);

        #pragma unroll
        for (int u = 0; u < 8; u++) {
            int r = ty*8 + u;
            #pragma unroll
            for (int p = 0; p < 4; p++) {
                int jb = colbase(tx, p);
                float2 f = *(float2*)(g_feat + (size_t)(n0+r)*128 + jb);
                float2 v = make_float2(f.x + f2lo(acc[u][p]) + sB2[jb],
                                       f.y + f2hi(acc[u][p]) + sB2[jb+1]);
                *(float2*)(g_feat + (size_t)(n0+r)*128 + jb) = v;
                if (write_out) *(float2*)(outp + (size_t)(n0+r)*128 + jb) = v;
            }
        }
        __syncthreads();
    }
}

// =======================================================================
// launch
// =======================================================================
extern "C" void kernel_launch(void* const* d_in, const int* in_sizes, int n_in,
                              void* d_out, int out_size) {
    const float* xyz   = (const float*)d_in[0];
    const float* feat0 = (const float*)d_in[1];
    const int*   knn   = (const int*)d_in[2];
    const float* offW1 = (const float*)d_in[3];
    const float* offb1 = (const float*)d_in[4];
    const float* offW2 = (const float*)d_in[5];
    const float* offb2 = (const float*)d_in[6];
    const float* eW1   = (const float*)d_in[7];
    const float* eb1   = (const float*)d_in[8];
    const float* eW2   = (const float*)d_in[9];
    const float* eb2   = (const float*)d_in[10];
    const float* uW1   = (const float*)d_in[11];
    const float* ub1   = (const float*)d_in[12];
    const float* uW2   = (const float*)d_in[13];
    const float* ub2   = (const float*)d_in[14];
    float* outp = (float*)d_out;

    const size_t SMEM_A  = (size_t)(16384*3 + 6144 + 384*4 + 128*2 + 16) * 4;  // 228,416 B
    const size_t SMEM_B  = (size_t)(16384*2 + 1024 + 128 + 128) * 4;           // 136,192 B
    const size_t SMEM_C1 = (size_t)(16384*3 + 128) * 4;                        // 197,120 B
    const size_t SMEM_C2 = (size_t)(16384*2 + 128) * 4;                        // 131,584 B

    cudaFuncSetAttribute(kA,  cudaFuncAttributeMaxDynamicSharedMemorySize, (int)SMEM_A);
    cudaFuncSetAttribute(kB,  cudaFuncAttributeMaxDynamicSharedMemorySize, (int)SMEM_B);
    cudaFuncSetAttribute(kC1, cudaFuncAttributeMaxDynamicSharedMemorySize, (int)SMEM_C1);
    cudaFuncSetAttribute(kC2, cudaFuncAttributeMaxDynamicSharedMemorySize, (int)SMEM_C2);

    cudaMemcpyToSymbolAsync(g_feat, feat0, sizeof(float)*BN*CC, 0, cudaMemcpyDeviceToDevice, 0);
    k_transpose<<<64, 256>>>(offW1, eW1, eW2, uW1, uW2);

    for (int t = 0; t < TT; t++) {
        kA<<<NSM, 256, SMEM_A>>>(xyz, offb1, offW2, offb2,
                                 eW1 + (size_t)t*CC*(3+CC), eb1 + (size_t)t*CC, t);
        kB<<<NSM, 256, SMEM_B>>>(knn, eb2 + (size_t)t*CC, t);
        kC1<<<NSM, 256, SMEM_C1>>>(ub1 + (size_t)t*CC, t);
        kC2<<<NSM, 256, SMEM_C2>>>(ub2 + (size_t)t*CC, outp, (t == TT-1) ? 1 : 0, t);
    }
}